// round 1
// baseline (speedup 1.0000x reference)
#include <cuda_runtime.h>
#include <math.h>

// Problem dims (fixed by the dataset)
#define BB   128
#define LL   1024
#define DK   128
#define DV   256
#define HH   256
#define NN   50
#define MM   (BB * LL)   // 131072 rows

// ------------------------- scratch (device globals; no allocs) -------------------------
__device__ float g_e[(size_t)MM * DV];      // sigmoid gate  (B*L, 256)
__device__ float g_a[(size_t)MM * DV];      // tanh gate     (B*L, 256)
__device__ float g_read[(size_t)MM * DV];   // scan reads    (B*L, 256)
__device__ float g_score[(size_t)MM * NN];  // softmax score (B*L, 50)

// =======================================================================================
// Kernel 1: score = softmax(problems @ w_key^T) over n=50.
// Thread-per-row, W_k staged in smem (broadcast reads), x via L1-resident LDG.128.
// =======================================================================================
__global__ void __launch_bounds__(256) score_kernel(const float* __restrict__ P,
                                                    const float* __restrict__ Wk,
                                                    float* __restrict__ S)
{
    __shared__ float ws[NN * DK];   // 25.6 KB
    int tid = threadIdx.x;
    for (int i = tid; i < NN * DK; i += 256) ws[i] = Wk[i];
    __syncthreads();

    int row = blockIdx.x * 256 + tid;
    const float4* xp = reinterpret_cast<const float4*>(P + (size_t)row * DK);

    float acc[NN];
#pragma unroll
    for (int n = 0; n < NN; ++n) acc[n] = 0.f;

    for (int k4 = 0; k4 < DK / 4; ++k4) {
        float4 x = xp[k4];
#pragma unroll
        for (int n = 0; n < NN; ++n) {
            float4 w = *reinterpret_cast<const float4*>(&ws[n * DK + k4 * 4]); // broadcast
            acc[n] = fmaf(x.x, w.x, fmaf(x.y, w.y, fmaf(x.z, w.z, fmaf(x.w, w.w, acc[n]))));
        }
    }

    // softmax over 50
    float mx = -1e30f;
#pragma unroll
    for (int n = 0; n < NN; ++n) mx = fmaxf(mx, acc[n]);
    float sum = 0.f;
#pragma unroll
    for (int n = 0; n < NN; ++n) { acc[n] = expf(acc[n] - mx); sum += acc[n]; }
    float inv = 1.f / sum;
    float* op = S + (size_t)row * NN;
#pragma unroll
    for (int n = 0; n < NN; ++n) op[n] = acc[n] * inv;
}

// =======================================================================================
// Kernel 2: generic C = act(A @ W^T + bias).
// A is split in K into two sources (A1 for k < k1len, A2 after) so the output GEMM can
// consume [reads | problems] without a concat. 128x128x8 tiles, 8x8 microtile,
// register-prefetch of next chunk. act: 0=sigmoid, 1=tanh.
// =======================================================================================
__global__ void __launch_bounds__(256, 2)
gemm_act_kernel(const float* __restrict__ A1, int lda1, int k1len,
                const float* __restrict__ A2, int lda2,
                const float* __restrict__ W,   // (N_total x K) row-major
                const float* __restrict__ bias,
                float* __restrict__ C, int ldc, int K, int act)
{
    __shared__ float As[8][132];
    __shared__ float Bs[8][132];

    const int tid = threadIdx.x;
    const int m0 = blockIdx.y * 128;
    const int n0 = blockIdx.x * 128;
    const int tx = tid & 15;     // n dir
    const int ty = tid >> 4;     // m dir

    const int ar = tid >> 1;
    const int ac = (tid & 1) * 4;

    auto loadA = [&](int k0) -> float4 {
        const float* src; int ld; int kk;
        if (k0 < k1len) { src = A1; ld = lda1; kk = k0; }
        else            { src = A2; ld = lda2; kk = k0 - k1len; }
        return *reinterpret_cast<const float4*>(&src[(size_t)(m0 + ar) * ld + kk + ac]);
    };
    auto loadW = [&](int k0) -> float4 {
        return *reinterpret_cast<const float4*>(&W[(size_t)(n0 + ar) * K + k0 + ac]);
    };

    float acc[8][8];
#pragma unroll
    for (int i = 0; i < 8; ++i)
#pragma unroll
        for (int j = 0; j < 8; ++j) acc[i][j] = 0.f;

    const int nch = K / 8;
    float4 av = loadA(0);
    float4 wv = loadW(0);

    for (int ch = 0; ch < nch; ++ch) {
        As[ac + 0][ar] = av.x; As[ac + 1][ar] = av.y;
        As[ac + 2][ar] = av.z; As[ac + 3][ar] = av.w;
        Bs[ac + 0][ar] = wv.x; Bs[ac + 1][ar] = wv.y;
        Bs[ac + 2][ar] = wv.z; Bs[ac + 3][ar] = wv.w;
        __syncthreads();

        if (ch + 1 < nch) { av = loadA((ch + 1) * 8); wv = loadW((ch + 1) * 8); }

#pragma unroll
        for (int kk = 0; kk < 8; ++kk) {
            float af[8], bf[8];
            *reinterpret_cast<float4*>(af)     = *reinterpret_cast<const float4*>(&As[kk][ty * 8]);
            *reinterpret_cast<float4*>(af + 4) = *reinterpret_cast<const float4*>(&As[kk][ty * 8 + 4]);
            *reinterpret_cast<float4*>(bf)     = *reinterpret_cast<const float4*>(&Bs[kk][tx * 8]);
            *reinterpret_cast<float4*>(bf + 4) = *reinterpret_cast<const float4*>(&Bs[kk][tx * 8 + 4]);
#pragma unroll
            for (int i = 0; i < 8; ++i)
#pragma unroll
                for (int j = 0; j < 8; ++j)
                    acc[i][j] = fmaf(af[i], bf[j], acc[i][j]);
        }
        __syncthreads();
    }

    float bv[8];
#pragma unroll
    for (int j = 0; j < 8; ++j) bv[j] = bias[n0 + tx * 8 + j];

#pragma unroll
    for (int i = 0; i < 8; ++i) {
        float outv[8];
#pragma unroll
        for (int j = 0; j < 8; ++j) {
            float v = acc[i][j] + bv[j];
            outv[j] = (act == 0) ? (1.f / (1.f + expf(-v))) : tanhf(v);
        }
        float* cp = &C[(size_t)(m0 + ty * 8 + i) * ldc + n0 + tx * 8];
        *reinterpret_cast<float4*>(cp)     = *reinterpret_cast<const float4*>(outv);
        *reinterpret_cast<float4*>(cp + 4) = *reinterpret_cast<const float4*>(outv + 4);
    }
}

// =======================================================================================
// Kernel 3: sequential scan. One CTA per batch; 256 threads; thread owns column d and
// keeps memory[0..49][d] in registers. Scores for step l+1 staged to smem, and e/a for
// step l+1 prefetched to regs, all under the compute of step l. One __syncthreads/step.
// =======================================================================================
__global__ void __launch_bounds__(256) scan_kernel(const float* __restrict__ S,
                                                   const float* __restrict__ E,
                                                   const float* __restrict__ A,
                                                   const float* __restrict__ M0,
                                                   float* __restrict__ R)
{
    const int b = blockIdx.x;
    const int d = threadIdx.x;
    __shared__ float sbuf[2][64];

    float m[NN];
#pragma unroll
    for (int n = 0; n < NN; ++n) m[n] = M0[n * DV + d];

    const float* sp = S + (size_t)b * LL * NN;
    const float* ep = E + (size_t)b * LL * DV + d;
    const float* ap = A + (size_t)b * LL * DV + d;
    float*       rp = R + (size_t)b * LL * DV + d;

    if (d < NN) sbuf[0][d] = sp[d];
    __syncthreads();
    float e = ep[0];
    float a = ap[0];

    for (int l = 0; l < LL; ++l) {
        const int nl = l + 1;
        // prefetch step l+1 operands (latency hidden under the 50-term loop below)
        if (d < NN && nl < LL) sbuf[nl & 1][d] = sp[(size_t)nl * NN + d];
        float en = (nl < LL) ? ep[(size_t)nl * DV] : 0.f;
        float an = (nl < LL) ? ap[(size_t)nl * DV] : 0.f;

        float r = 0.f;
        const float ne = -e;
        const float* sb = sbuf[l & 1];
#pragma unroll
        for (int n = 0; n < NN; ++n) {
            float s = sb[n];                 // smem broadcast
            r = fmaf(s, m[n], r);            // read uses pre-update memory
            float q = s * ne;
            m[n] = fmaf(q, m[n], m[n]);      // m *= (1 - s*e)
            m[n] = fmaf(s, a, m[n]);         // m += s*a
        }
        rp[(size_t)l * DV] = r;

        __syncthreads();                     // publish staged scores for next step
        e = en; a = an;
    }
}

// =======================================================================================
// Launch
// =======================================================================================
extern "C" void kernel_launch(void* const* d_in, const int* in_sizes, int n_in,
                              void* d_out, int out_size)
{
    const float* problems     = (const float*)d_in[0];
    const float* interactions = (const float*)d_in[1];
    const float* w_key        = (const float*)d_in[2];
    const float* w_erase_w    = (const float*)d_in[3];
    const float* w_erase_b    = (const float*)d_in[4];
    const float* w_add_w      = (const float*)d_in[5];
    const float* w_add_b      = (const float*)d_in[6];
    const float* w_out_w      = (const float*)d_in[7];
    const float* w_out_b      = (const float*)d_in[8];
    const float* init_memory  = (const float*)d_in[9];
    float* out = (float*)d_out;

    float *ge, *ga, *gr, *gs;
    cudaGetSymbolAddress((void**)&ge, g_e);
    cudaGetSymbolAddress((void**)&ga, g_a);
    cudaGetSymbolAddress((void**)&gr, g_read);
    cudaGetSymbolAddress((void**)&gs, g_score);

    // 1) attention scores (softmax over 50 slots)
    score_kernel<<<MM / 256, 256>>>(problems, w_key, gs);

    // 2) gates: e = sigmoid(X We^T + be), a = tanh(X Wa^T + ba)
    dim3 gg(DV / 128, MM / 128);
    gemm_act_kernel<<<gg, 256>>>(interactions, DV, DV, interactions, DV,
                                 w_erase_w, w_erase_b, ge, DV, DV, /*sigmoid*/0);
    gemm_act_kernel<<<gg, 256>>>(interactions, DV, DV, interactions, DV,
                                 w_add_w, w_add_b, ga, DV, DV, /*tanh*/1);

    // 3) sequential memory scan (batch-parallel)
    scan_kernel<<<BB, 256>>>(gs, ge, ga, init_memory, gr);

    // 4) out = tanh([reads | problems] @ Wo^T + bo)  (K split 256 + 128)
    gemm_act_kernel<<<gg, 256>>>(gr, DV, DV, problems, DK,
                                 w_out_w, w_out_b, out, HH, DV + DK, /*tanh*/1);
}

// round 2
// speedup vs baseline: 1.2043x; 1.2043x over previous
#include <cuda_runtime.h>
#include <math.h>

// Problem dims (fixed by the dataset)
#define BB   128
#define LL   1024
#define DK   128
#define DV   256
#define HH   256
#define NN   50
#define MM   (BB * LL)   // 131072 rows

typedef unsigned long long u64;

// ---------------- packed f32x2 helpers (ptxas never emits these from C++) ----------------
__device__ __forceinline__ u64 fma2(u64 a, u64 b, u64 c) {
    u64 d;
    asm("fma.rn.f32x2 %0, %1, %2, %3;" : "=l"(d) : "l"(a), "l"(b), "l"(c));
    return d;
}
__device__ __forceinline__ u64 pack2(float lo, float hi) {
    u64 r;
    asm("mov.b64 %0, {%1, %2};" : "=l"(r) : "f"(lo), "f"(hi));
    return r;
}
__device__ __forceinline__ float2 unpack2(u64 v) {
    float2 r;
    asm("mov.b64 {%0, %1}, %2;" : "=f"(r.x), "=f"(r.y) : "l"(v));
    return r;
}

// ------------------------- scratch (device globals; no allocs) -------------------------
__device__ float g_e[(size_t)MM * DV];      // sigmoid gate  (B*L, 256)
__device__ float g_a[(size_t)MM * DV];      // tanh gate     (B*L, 256)
__device__ float g_read[(size_t)MM * DV];   // scan reads    (B*L, 256)
__device__ float g_score[(size_t)MM * NN];  // softmax score (B*L, 50)

// =======================================================================================
// Kernel 1: score = softmax(problems @ w_key^T) over n=50. Packed along K.
// =======================================================================================
__global__ void __launch_bounds__(256) score_kernel(const float* __restrict__ P,
                                                    const float* __restrict__ Wk,
                                                    float* __restrict__ S)
{
    __shared__ float ws[NN * DK];   // 25.6 KB
    int tid = threadIdx.x;
    for (int i = tid; i < NN * DK; i += 256) ws[i] = Wk[i];
    __syncthreads();

    int row = blockIdx.x * 256 + tid;
    const float4* xp = reinterpret_cast<const float4*>(P + (size_t)row * DK);

    u64 acc2[NN];
#pragma unroll
    for (int n = 0; n < NN; ++n) acc2[n] = 0ull;

    for (int k4 = 0; k4 < DK / 4; ++k4) {
        float4 x = xp[k4];
        u64 x01 = pack2(x.x, x.y);
        u64 x23 = pack2(x.z, x.w);
#pragma unroll
        for (int n = 0; n < NN; ++n) {
            const u64* wrow = reinterpret_cast<const u64*>(&ws[n * DK]);
            acc2[n] = fma2(x01, wrow[k4 * 2 + 0], acc2[n]);
            acc2[n] = fma2(x23, wrow[k4 * 2 + 1], acc2[n]);
        }
    }

    float acc[NN];
#pragma unroll
    for (int n = 0; n < NN; ++n) { float2 v = unpack2(acc2[n]); acc[n] = v.x + v.y; }

    // softmax over 50
    float mx = -1e30f;
#pragma unroll
    for (int n = 0; n < NN; ++n) mx = fmaxf(mx, acc[n]);
    float sum = 0.f;
#pragma unroll
    for (int n = 0; n < NN; ++n) { acc[n] = expf(acc[n] - mx); sum += acc[n]; }
    float inv = 1.f / sum;
    float* op = S + (size_t)row * NN;
#pragma unroll
    for (int n = 0; n < NN; ++n) op[n] = acc[n] * inv;
}

// =======================================================================================
// Kernel 2: C = act(A @ W^T + bias), packed-f32x2 inner loop.
// A staged DUPLICATED in smem so the packed A operand is a straight LDS.128.
// K split into two sources (A1 for k < k1len, A2 after). act: 0=sigmoid, 1=tanh.
// =======================================================================================
__global__ void __launch_bounds__(256, 2)
gemm_act_kernel(const float* __restrict__ A1, int lda1, int k1len,
                const float* __restrict__ A2, int lda2,
                const float* __restrict__ W,   // (N_total x K) row-major
                const float* __restrict__ bias,
                float* __restrict__ C, int ldc, int K, int act)
{
    __shared__ float As2[8][264];   // duplicated A values: [k][2m],[k][2m+1]
    __shared__ float Bs[8][132];

    const int tid = threadIdx.x;
    const int m0 = blockIdx.y * 128;
    const int n0 = blockIdx.x * 128;
    const int tx = tid & 15;     // n dir
    const int ty = tid >> 4;     // m dir

    const int ar = tid >> 1;
    const int ac = (tid & 1) * 4;

    auto loadA = [&](int k0) -> float4 {
        const float* src; int ld; int kk;
        if (k0 < k1len) { src = A1; ld = lda1; kk = k0; }
        else            { src = A2; ld = lda2; kk = k0 - k1len; }
        return *reinterpret_cast<const float4*>(&src[(size_t)(m0 + ar) * ld + kk + ac]);
    };
    auto loadW = [&](int k0) -> float4 {
        return *reinterpret_cast<const float4*>(&W[(size_t)(n0 + ar) * K + k0 + ac]);
    };

    u64 acc2[8][4];
#pragma unroll
    for (int i = 0; i < 8; ++i)
#pragma unroll
        for (int j = 0; j < 4; ++j) acc2[i][j] = 0ull;

    const int nch = K / 8;
    float4 av = loadA(0);
    float4 wv = loadW(0);

    for (int ch = 0; ch < nch; ++ch) {
        // stage A duplicated (4x STS.64), W plain (4x STS.32)
#pragma unroll
        for (int q = 0; q < 4; ++q) {
            float v = (&av.x)[q];
            *reinterpret_cast<float2*>(&As2[ac + q][2 * ar]) = make_float2(v, v);
        }
        Bs[ac + 0][ar] = wv.x; Bs[ac + 1][ar] = wv.y;
        Bs[ac + 2][ar] = wv.z; Bs[ac + 3][ar] = wv.w;
        __syncthreads();

        if (ch + 1 < nch) { av = loadA((ch + 1) * 8); wv = loadW((ch + 1) * 8); }

#pragma unroll
        for (int kk = 0; kk < 8; ++kk) {
            u64 af2[8], bf2[4];
            const ulonglong2* ap2 = reinterpret_cast<const ulonglong2*>(&As2[kk][ty * 16]);
            ulonglong2 v0 = ap2[0], v1 = ap2[1], v2 = ap2[2], v3 = ap2[3];
            af2[0] = v0.x; af2[1] = v0.y; af2[2] = v1.x; af2[3] = v1.y;
            af2[4] = v2.x; af2[5] = v2.y; af2[6] = v3.x; af2[7] = v3.y;
            const ulonglong2* bp2 = reinterpret_cast<const ulonglong2*>(&Bs[kk][tx * 8]);
            ulonglong2 b0 = bp2[0], b1 = bp2[1];
            bf2[0] = b0.x; bf2[1] = b0.y; bf2[2] = b1.x; bf2[3] = b1.y;
#pragma unroll
            for (int i = 0; i < 8; ++i)
#pragma unroll
                for (int j = 0; j < 4; ++j)
                    acc2[i][j] = fma2(af2[i], bf2[j], acc2[i][j]);
        }
        __syncthreads();
    }

    float bv[8];
#pragma unroll
    for (int j = 0; j < 8; ++j) bv[j] = bias[n0 + tx * 8 + j];

#pragma unroll
    for (int i = 0; i < 8; ++i) {
        float outv[8];
#pragma unroll
        for (int j = 0; j < 4; ++j) {
            float2 c = unpack2(acc2[i][j]);
            float v0 = c.x + bv[2 * j];
            float v1 = c.y + bv[2 * j + 1];
            outv[2 * j]     = (act == 0) ? (1.f / (1.f + expf(-v0))) : tanhf(v0);
            outv[2 * j + 1] = (act == 0) ? (1.f / (1.f + expf(-v1))) : tanhf(v1);
        }
        float* cp = &C[(size_t)(m0 + ty * 8 + i) * ldc + n0 + tx * 8];
        *reinterpret_cast<float4*>(cp)     = *reinterpret_cast<const float4*>(outv);
        *reinterpret_cast<float4*>(cp + 4) = *reinterpret_cast<const float4*>(outv + 4);
    }
}

// =======================================================================================
// Kernel 3: sequential scan, packed f32x2. One CTA per batch; 128 threads; thread owns
// column PAIR (2t, 2t+1); memory state = 50 packed f32x2 registers. Scores double-buffered
// in smem, e/a for step l+1 prefetched under step l's compute. One barrier per step.
// =======================================================================================
__global__ void __launch_bounds__(128) scan_kernel(const float* __restrict__ S,
                                                   const float* __restrict__ E,
                                                   const float* __restrict__ A,
                                                   const float* __restrict__ M0,
                                                   float* __restrict__ R)
{
    const int b = blockIdx.x;
    const int t = threadIdx.x;            // column pair (2t, 2t+1)
    __shared__ float sbuf[2][64];

    u64 m[NN];
#pragma unroll
    for (int n = 0; n < NN; ++n) {
        float2 mv = *reinterpret_cast<const float2*>(&M0[n * DV + 2 * t]);
        m[n] = pack2(mv.x, mv.y);
    }

    const float* sp = S + (size_t)b * LL * NN;
    const float* ep = E + (size_t)b * LL * DV + 2 * t;
    const float* ap = A + (size_t)b * LL * DV + 2 * t;
    float*       rp = R + (size_t)b * LL * DV + 2 * t;

    if (t < NN) sbuf[0][t] = sp[t];
    __syncthreads();
    float2 e = *reinterpret_cast<const float2*>(ep);
    float2 a = *reinterpret_cast<const float2*>(ap);

    for (int l = 0; l < LL; ++l) {
        const int nl = (l + 1 < LL) ? (l + 1) : (LL - 1);
        // prefetch step l+1 operands (latency hidden under the 50-slot loop below)
        if (t < NN) sbuf[(l + 1) & 1][t] = sp[(size_t)nl * NN + t];
        float2 en = *reinterpret_cast<const float2*>(ep + (size_t)nl * DV);
        float2 an = *reinterpret_cast<const float2*>(ap + (size_t)nl * DV);

        u64 apk  = pack2(a.x, a.y);
        u64 nepk = pack2(-e.x, -e.y);
        u64 r = 0ull;
        const float* sb = sbuf[l & 1];
#pragma unroll
        for (int n = 0; n < NN; ++n) {
            float s = sb[n];                 // smem broadcast
            u64 spk = pack2(s, s);
            r = fma2(spk, m[n], r);          // read uses pre-update memory
            u64 tt = fma2(nepk, m[n], apk);  // a - e*m
            m[n] = fma2(spk, tt, m[n]);      // m += s*(a - e*m)
        }
        float2 rv = unpack2(r);
        *reinterpret_cast<float2*>(rp + (size_t)l * DV) = rv;

        __syncthreads();                     // publish staged scores for next step
        e = en; a = an;
    }
}

// =======================================================================================
// Launch
// =======================================================================================
extern "C" void kernel_launch(void* const* d_in, const int* in_sizes, int n_in,
                              void* d_out, int out_size)
{
    const float* problems     = (const float*)d_in[0];
    const float* interactions = (const float*)d_in[1];
    const float* w_key        = (const float*)d_in[2];
    const float* w_erase_w    = (const float*)d_in[3];
    const float* w_erase_b    = (const float*)d_in[4];
    const float* w_add_w      = (const float*)d_in[5];
    const float* w_add_b      = (const float*)d_in[6];
    const float* w_out_w      = (const float*)d_in[7];
    const float* w_out_b      = (const float*)d_in[8];
    const float* init_memory  = (const float*)d_in[9];
    float* out = (float*)d_out;

    float *ge, *ga, *gr, *gs;
    cudaGetSymbolAddress((void**)&ge, g_e);
    cudaGetSymbolAddress((void**)&ga, g_a);
    cudaGetSymbolAddress((void**)&gr, g_read);
    cudaGetSymbolAddress((void**)&gs, g_score);

    // 1) attention scores (softmax over 50 slots)
    score_kernel<<<MM / 256, 256>>>(problems, w_key, gs);

    // 2) gates: e = sigmoid(X We^T + be), a = tanh(X Wa^T + ba)
    dim3 gg(DV / 128, MM / 128);
    gemm_act_kernel<<<gg, 256>>>(interactions, DV, DV, interactions, DV,
                                 w_erase_w, w_erase_b, ge, DV, DV, /*sigmoid*/0);
    gemm_act_kernel<<<gg, 256>>>(interactions, DV, DV, interactions, DV,
                                 w_add_w, w_add_b, ga, DV, DV, /*tanh*/1);

    // 3) sequential memory scan (batch-parallel)
    scan_kernel<<<BB, 128>>>(gs, ge, ga, init_memory, gr);

    // 4) out = tanh([reads | problems] @ Wo^T + bo)  (K split 256 + 128)
    gemm_act_kernel<<<gg, 256>>>(gr, DV, DV, problems, DK,
                                 w_out_w, w_out_b, out, HH, DV + DK, /*tanh*/1);
}

// round 4
// speedup vs baseline: 2.2096x; 1.8348x over previous
#include <cuda_runtime.h>
#include <cuda_bf16.h>
#include <math.h>
#include <stdint.h>

#define BB   128
#define LL   1024
#define DK   128
#define DV   256
#define HH   256
#define NN   50
#define MM   (BB * LL)   // 131072 rows

typedef unsigned long long u64;

// ---------------- packed f32x2 helpers ----------------
__device__ __forceinline__ u64 fma2(u64 a, u64 b, u64 c) {
    u64 d; asm("fma.rn.f32x2 %0, %1, %2, %3;" : "=l"(d) : "l"(a), "l"(b), "l"(c)); return d;
}
__device__ __forceinline__ u64 add2(u64 a, u64 b) {
    u64 d; asm("add.rn.f32x2 %0, %1, %2;" : "=l"(d) : "l"(a), "l"(b)); return d;
}
__device__ __forceinline__ u64 pack2(float lo, float hi) {
    u64 r; asm("mov.b64 %0, {%1, %2};" : "=l"(r) : "f"(lo), "f"(hi)); return r;
}
__device__ __forceinline__ float2 unpack2(u64 v) {
    float2 r; asm("mov.b64 {%0, %1}, %2;" : "=f"(r.x), "=f"(r.y) : "l"(v)); return r;
}

// ---------------- async / smem helpers ----------------
__device__ __forceinline__ uint32_t smem_u32(const void* p) {
    uint32_t a;
    asm("{ .reg .u64 t; cvta.to.shared.u64 t, %1; cvt.u32.u64 %0, t; }" : "=r"(a) : "l"(p));
    return a;
}
__device__ __forceinline__ void cpasync16(uint32_t saddr, const void* gptr) {
    asm volatile("cp.async.cg.shared.global [%0], [%1], 16;" :: "r"(saddr), "l"(gptr) : "memory");
}
__device__ __forceinline__ void cpasync4(uint32_t saddr, const void* gptr) {
    asm volatile("cp.async.ca.shared.global [%0], [%1], 4;" :: "r"(saddr), "l"(gptr) : "memory");
}
__device__ __forceinline__ uint32_t lds32(uint32_t addr) {
    uint32_t v; asm volatile("ld.shared.b32 %0, [%1];" : "=r"(v) : "r"(addr)); return v;
}
__device__ __forceinline__ void mma16816(float* c, const uint32_t* a, const uint32_t* b) {
    asm volatile(
        "mma.sync.aligned.m16n8k16.row.col.f32.bf16.bf16.f32 "
        "{%0,%1,%2,%3}, {%4,%5,%6,%7}, {%8,%9}, {%0,%1,%2,%3};"
        : "+f"(c[0]), "+f"(c[1]), "+f"(c[2]), "+f"(c[3])
        : "r"(a[0]), "r"(a[1]), "r"(a[2]), "r"(a[3]), "r"(b[0]), "r"(b[1]));
}

// ------------------------- scratch (device globals; no allocs) -------------------------
__device__ float          g_e[(size_t)MM * DV];
__device__ float          g_a[(size_t)MM * DV];
__device__ float          g_score[(size_t)MM * NN];
__device__ __nv_bfloat16  g_ibhi[(size_t)MM * DV], g_iblo[(size_t)MM * DV];   // interactions
__device__ __nv_bfloat16  g_pbhi[(size_t)MM * DK], g_pblo[(size_t)MM * DK];   // problems
__device__ __nv_bfloat16  g_rhi[(size_t)MM * DV],  g_rlo[(size_t)MM * DV];    // scan reads
__device__ __nv_bfloat16  g_wehi[DV * DV], g_welo[DV * DV];
__device__ __nv_bfloat16  g_wahi[DV * DV], g_walo[DV * DV];
__device__ __nv_bfloat16  g_wohi[HH * (DV + DK)], g_wolo[HH * (DV + DK)];

// =======================================================================================
// f32 -> bf16 hi/lo split conversion
// =======================================================================================
__global__ void __launch_bounds__(256) conv_kernel(const float* __restrict__ x,
                                                   __nv_bfloat16* __restrict__ hi,
                                                   __nv_bfloat16* __restrict__ lo,
                                                   int n4)
{
    int i = blockIdx.x * 256 + threadIdx.x;
    if (i >= n4) return;
    float4 v = reinterpret_cast<const float4*>(x)[i];
    ushort4 h, l;
    __nv_bfloat16 b; float f;
    b = __float2bfloat16(v.x); h.x = __bfloat16_as_ushort(b); f = v.x - __bfloat162float(b);
    l.x = __bfloat16_as_ushort(__float2bfloat16(f));
    b = __float2bfloat16(v.y); h.y = __bfloat16_as_ushort(b); f = v.y - __bfloat162float(b);
    l.y = __bfloat16_as_ushort(__float2bfloat16(f));
    b = __float2bfloat16(v.z); h.z = __bfloat16_as_ushort(b); f = v.z - __bfloat162float(b);
    l.z = __bfloat16_as_ushort(__float2bfloat16(f));
    b = __float2bfloat16(v.w); h.w = __bfloat16_as_ushort(b); f = v.w - __bfloat162float(b);
    l.w = __bfloat16_as_ushort(__float2bfloat16(f));
    reinterpret_cast<ushort4*>(hi)[i] = h;
    reinterpret_cast<ushort4*>(lo)[i] = l;
}

// =======================================================================================
// score = softmax(problems @ w_key^T) over n=50 (packed f32x2 along K)
// =======================================================================================
__global__ void __launch_bounds__(256) score_kernel(const float* __restrict__ P,
                                                    const float* __restrict__ Wk,
                                                    float* __restrict__ S)
{
    __shared__ float ws[NN * DK];
    int tid = threadIdx.x;
    for (int i = tid; i < NN * DK; i += 256) ws[i] = Wk[i];
    __syncthreads();

    int row = blockIdx.x * 256 + tid;
    const float4* xp = reinterpret_cast<const float4*>(P + (size_t)row * DK);

    u64 acc2[NN];
#pragma unroll
    for (int n = 0; n < NN; ++n) acc2[n] = 0ull;

    for (int k4 = 0; k4 < DK / 4; ++k4) {
        float4 x = xp[k4];
        u64 x01 = pack2(x.x, x.y);
        u64 x23 = pack2(x.z, x.w);
#pragma unroll
        for (int n = 0; n < NN; ++n) {
            const u64* wrow = reinterpret_cast<const u64*>(&ws[n * DK]);
            acc2[n] = fma2(x01, wrow[k4 * 2 + 0], acc2[n]);
            acc2[n] = fma2(x23, wrow[k4 * 2 + 1], acc2[n]);
        }
    }

    float acc[NN];
#pragma unroll
    for (int n = 0; n < NN; ++n) { float2 v = unpack2(acc2[n]); acc[n] = v.x + v.y; }

    float mx = -1e30f;
#pragma unroll
    for (int n = 0; n < NN; ++n) mx = fmaxf(mx, acc[n]);
    float sum = 0.f;
#pragma unroll
    for (int n = 0; n < NN; ++n) { acc[n] = expf(acc[n] - mx); sum += acc[n]; }
    float inv = 1.f / sum;
    float* op = S + (size_t)row * NN;
#pragma unroll
    for (int n = 0; n < NN; ++n) op[n] = acc[n] * inv;
}

// =======================================================================================
// HMMA bf16 hi/lo 3-pass GEMM: C = act(A @ W^T + bias).
// CTA tile 128x128, warp tile 32x64, K-chunk 32, cp.async double buffer.
// A split in K across two sources at k1len (chunk-aligned).
// smem rows padded to 80B (40 bf16): bank-conflict-free frag loads (g*20+t distinct mod 32).
// =======================================================================================
#define GP   40        // row pitch in bf16 (80 bytes)
#define MATB 10240u    // bytes per matrix tile (128*80)
#define BUFB 40960u    // bytes per double-buffer stage (4 matrices)

__global__ void __launch_bounds__(256)
gemm_hmma(const __nv_bfloat16* __restrict__ a1hi, const __nv_bfloat16* __restrict__ a1lo,
          int lda1, int k1len,
          const __nv_bfloat16* __restrict__ a2hi, const __nv_bfloat16* __restrict__ a2lo,
          int lda2,
          const __nv_bfloat16* __restrict__ bhi, const __nv_bfloat16* __restrict__ blo,
          int K,
          const float* __restrict__ bias, float* __restrict__ C, int act)
{
    extern __shared__ __align__(16) char dsm[];
    const uint32_t dbase = smem_u32(dsm);

    const int tid = threadIdx.x;
    const int m0 = blockIdx.x * 128;
    const int n0 = blockIdx.y * 128;
    const int wid = tid >> 5;
    const int lane = tid & 31;
    const int g  = lane >> 2;
    const int t2 = (lane & 3) * 2;
    const int warpM = (wid & 3) * 32;
    const int warpN = (wid >> 2) * 64;

    const int nch = K / 32;

    auto load_chunk = [&](int c) {
        uint32_t sb = dbase + (uint32_t)(c & 1) * BUFB;
        int k0 = c * 32;
        const __nv_bfloat16 *shi, *slo; int ld, kk;
        if (k0 < k1len) { shi = a1hi; slo = a1lo; ld = lda1; kk = k0; }
        else            { shi = a2hi; slo = a2lo; ld = lda2; kk = k0 - k1len; }
#pragma unroll
        for (int i = 0; i < 2; ++i) {
            int gidx = tid + 256 * i;            // 0..511
            int row = gidx >> 2, seg = gidx & 3;
            uint32_t so = (uint32_t)(row * 80 + seg * 16);
            size_t gA = (size_t)(m0 + row) * ld + kk + seg * 8;
            cpasync16(sb + so,            shi + gA);
            cpasync16(sb + MATB + so,     slo + gA);
            size_t gB = (size_t)(n0 + row) * K + k0 + seg * 8;
            cpasync16(sb + 2 * MATB + so, bhi + gB);
            cpasync16(sb + 3 * MATB + so, blo + gB);
        }
        asm volatile("cp.async.commit_group;" ::: "memory");
    };

    float acc[2][8][4];
#pragma unroll
    for (int mt = 0; mt < 2; ++mt)
#pragma unroll
        for (int nt = 0; nt < 8; ++nt)
#pragma unroll
            for (int q = 0; q < 4; ++q) acc[mt][nt][q] = 0.f;

    load_chunk(0);

    for (int c = 0; c < nch; ++c) {
        if (c + 1 < nch) {
            load_chunk(c + 1);
            asm volatile("cp.async.wait_group 1;" ::: "memory");
        } else {
            asm volatile("cp.async.wait_group 0;" ::: "memory");
        }
        __syncthreads();

        uint32_t sb = dbase + (uint32_t)(c & 1) * BUFB;
#pragma unroll
        for (int ks = 0; ks < 2; ++ks) {
            const uint32_t cb = (uint32_t)((ks * 16 + t2) * 2);   // byte col offset
            uint32_t a_h[2][4], a_l[2][4];
#pragma unroll
            for (int mt = 0; mt < 2; ++mt) {
                uint32_t r0 = sb + (uint32_t)((warpM + mt * 16 + g) * 80) + cb;
                uint32_t r8 = r0 + 8 * 80;
                a_h[mt][0] = lds32(r0);        a_h[mt][1] = lds32(r8);
                a_h[mt][2] = lds32(r0 + 16);   a_h[mt][3] = lds32(r8 + 16);
                a_l[mt][0] = lds32(r0 + MATB); a_l[mt][1] = lds32(r8 + MATB);
                a_l[mt][2] = lds32(r0 + MATB + 16); a_l[mt][3] = lds32(r8 + MATB + 16);
            }
            uint32_t b_h[8][2], b_l[8][2];
#pragma unroll
            for (int nt = 0; nt < 8; ++nt) {
                uint32_t rr = sb + 2 * MATB + (uint32_t)((warpN + nt * 8 + g) * 80) + cb;
                b_h[nt][0] = lds32(rr);        b_h[nt][1] = lds32(rr + 16);
                b_l[nt][0] = lds32(rr + MATB); b_l[nt][1] = lds32(rr + MATB + 16);
            }
#pragma unroll
            for (int mt = 0; mt < 2; ++mt)
#pragma unroll
                for (int nt = 0; nt < 8; ++nt) {
                    mma16816(acc[mt][nt], a_h[mt], b_h[nt]);
                    mma16816(acc[mt][nt], a_h[mt], b_l[nt]);
                    mma16816(acc[mt][nt], a_l[mt], b_h[nt]);
                }
        }
        __syncthreads();
    }

    // epilogue: bias + activation, direct STG.64 (each quad covers one 32B sector)
#pragma unroll
    for (int mt = 0; mt < 2; ++mt) {
        int r0 = m0 + warpM + mt * 16 + g;
#pragma unroll
        for (int nt = 0; nt < 8; ++nt) {
            int cc = n0 + warpN + nt * 8 + t2;
            float b0 = bias[cc], b1 = bias[cc + 1];
            float v0 = acc[mt][nt][0] + b0, v1 = acc[mt][nt][1] + b1;
            float v2 = acc[mt][nt][2] + b0, v3 = acc[mt][nt][3] + b1;
            if (act == 0) {
                v0 = __fdividef(1.f, 1.f + __expf(-v0));
                v1 = __fdividef(1.f, 1.f + __expf(-v1));
                v2 = __fdividef(1.f, 1.f + __expf(-v2));
                v3 = __fdividef(1.f, 1.f + __expf(-v3));
            } else {
                v0 = tanhf(v0); v1 = tanhf(v1); v2 = tanhf(v2); v3 = tanhf(v3);
            }
            *reinterpret_cast<float2*>(&C[(size_t)r0 * 256 + cc])       = make_float2(v0, v1);
            *reinterpret_cast<float2*>(&C[(size_t)(r0 + 8) * 256 + cc]) = make_float2(v2, v3);
        }
    }
}

// =======================================================================================
// Scan: 256 threads/CTA (thread = column d), slots packed in 25 f32x2 pairs.
// Score staging via 4-deep cp.async ring; e/a via depth-3 register pipeline.
// Emits reads as bf16 hi/lo for the output GEMM.
// =======================================================================================
__global__ void __launch_bounds__(256) scan_kernel(const float* __restrict__ S,
                                                   const float* __restrict__ E,
                                                   const float* __restrict__ A,
                                                   const float* __restrict__ M0,
                                                   __nv_bfloat16* __restrict__ Rhi,
                                                   __nv_bfloat16* __restrict__ Rlo)
{
    const int b = blockIdx.x;
    const int d = threadIdx.x;
    __shared__ __align__(16) float ring[4][52];

    u64 m[25];
#pragma unroll
    for (int j = 0; j < 25; ++j)
        m[j] = pack2(M0[(2 * j) * DV + d], M0[(2 * j + 1) * DV + d]);

    const float* sp = S + (size_t)b * LL * NN;
    const float* ep = E + (size_t)b * LL * DV + d;
    const float* ap = A + (size_t)b * LL * DV + d;
    __nv_bfloat16* rh = Rhi + (size_t)b * LL * DV + d;
    __nv_bfloat16* rl = Rlo + (size_t)b * LL * DV + d;

    // preload score ring for steps 0..2 (3 groups in flight)
    if (d < NN) {
#pragma unroll
        for (int p = 0; p < 3; ++p) {
            cpasync4(smem_u32(&ring[p][d]), sp + (size_t)p * NN + d);
            asm volatile("cp.async.commit_group;" ::: "memory");
        }
        asm volatile("cp.async.wait_group 2;" ::: "memory");   // step-0 group done
    }
    // e/a register pipeline: steps 0,1,2
    float e0 = ep[0],        a0 = ap[0];
    float e1 = ep[DV],       a1 = ap[DV];
    float e2 = ep[2 * DV],   a2 = ap[2 * DV];
    __syncthreads();

    for (int l = 0; l < LL; ++l) {
        const int n3 = (l + 3 < LL) ? (l + 3) : (LL - 1);
        if (d < NN) {
            cpasync4(smem_u32(&ring[(l + 3) & 3][d]), sp + (size_t)n3 * NN + d);
            asm volatile("cp.async.commit_group;" ::: "memory");
        }
        float en = ep[(size_t)n3 * DV];
        float an = ap[(size_t)n3 * DV];

        u64 apk  = pack2(a0, a0);
        u64 nepk = pack2(-e0, -e0);
        u64 r0 = 0ull, r1 = 0ull;
        const u64* sb = reinterpret_cast<const u64*>(ring[l & 3]);
#pragma unroll
        for (int j = 0; j < 25; ++j) {
            u64 spk = sb[j];                  // LDS.64 broadcast
            if (j & 1) r1 = fma2(spk, m[j], r1);
            else       r0 = fma2(spk, m[j], r0);
            u64 tt = fma2(nepk, m[j], apk);   // a - e*m
            m[j] = fma2(spk, tt, m[j]);       // m += s*(a - e*m)
        }
        float2 rv = unpack2(add2(r0, r1));
        float rr = rv.x + rv.y;
        __nv_bfloat16 h  = __float2bfloat16(rr);
        __nv_bfloat16 lo = __float2bfloat16(rr - __bfloat162float(h));
        rh[(size_t)l * DV] = h;
        rl[(size_t)l * DV] = lo;

        if (d < NN) asm volatile("cp.async.wait_group 2;" ::: "memory");
        __syncthreads();
        e0 = e1; a0 = a1; e1 = e2; a1 = a2; e2 = en; a2 = an;
    }
}

// =======================================================================================
// Launch
// =======================================================================================
extern "C" void kernel_launch(void* const* d_in, const int* in_sizes, int n_in,
                              void* d_out, int out_size)
{
    const float* problems     = (const float*)d_in[0];
    const float* interactions = (const float*)d_in[1];
    const float* w_key        = (const float*)d_in[2];
    const float* w_erase_w    = (const float*)d_in[3];
    const float* w_erase_b    = (const float*)d_in[4];
    const float* w_add_w      = (const float*)d_in[5];
    const float* w_add_b      = (const float*)d_in[6];
    const float* w_out_w      = (const float*)d_in[7];
    const float* w_out_b      = (const float*)d_in[8];
    const float* init_memory  = (const float*)d_in[9];
    float* out = (float*)d_out;

    float *ge, *ga, *gs;
    __nv_bfloat16 *ibhi, *iblo, *pbhi, *pblo, *rhi, *rlo;
    __nv_bfloat16 *wehi, *welo, *wahi, *walo, *wohi, *wolo;
    cudaGetSymbolAddress((void**)&ge,   g_e);
    cudaGetSymbolAddress((void**)&ga,   g_a);
    cudaGetSymbolAddress((void**)&gs,   g_score);
    cudaGetSymbolAddress((void**)&ibhi, g_ibhi);  cudaGetSymbolAddress((void**)&iblo, g_iblo);
    cudaGetSymbolAddress((void**)&pbhi, g_pbhi);  cudaGetSymbolAddress((void**)&pblo, g_pblo);
    cudaGetSymbolAddress((void**)&rhi,  g_rhi);   cudaGetSymbolAddress((void**)&rlo,  g_rlo);
    cudaGetSymbolAddress((void**)&wehi, g_wehi);  cudaGetSymbolAddress((void**)&welo, g_welo);
    cudaGetSymbolAddress((void**)&wahi, g_wahi);  cudaGetSymbolAddress((void**)&walo, g_walo);
    cudaGetSymbolAddress((void**)&wohi, g_wohi);  cudaGetSymbolAddress((void**)&wolo, g_wolo);

    cudaFuncSetAttribute(gemm_hmma, cudaFuncAttributeMaxDynamicSharedMemorySize, 2 * BUFB);

    // conversions (f32 -> bf16 hi/lo)
    conv_kernel<<<(MM * DV / 4 + 255) / 256, 256>>>(interactions, ibhi, iblo, MM * DV / 4);
    conv_kernel<<<(MM * DK / 4 + 255) / 256, 256>>>(problems, pbhi, pblo, MM * DK / 4);
    conv_kernel<<<(DV * DV / 4 + 255) / 256, 256>>>(w_erase_w, wehi, welo, DV * DV / 4);
    conv_kernel<<<(DV * DV / 4 + 255) / 256, 256>>>(w_add_w, wahi, walo, DV * DV / 4);
    conv_kernel<<<(HH * (DV + DK) / 4 + 255) / 256, 256>>>(w_out_w, wohi, wolo, HH * (DV + DK) / 4);

    // attention scores
    score_kernel<<<MM / 256, 256>>>(problems, w_key, gs);

    // gate GEMMs on tensor cores (HMMA)
    dim3 gg(MM / 128, 2);
    gemm_hmma<<<gg, 256, 2 * BUFB>>>(ibhi, iblo, DV, DV, ibhi, iblo, DV,
                                     wehi, welo, DV, w_erase_b, ge, /*sigmoid*/0);
    gemm_hmma<<<gg, 256, 2 * BUFB>>>(ibhi, iblo, DV, DV, ibhi, iblo, DV,
                                     wahi, walo, DV, w_add_b, ga, /*tanh*/1);

    // sequential memory scan
    scan_kernel<<<BB, 256>>>(gs, ge, ga, init_memory, rhi, rlo);

    // output GEMM: A = [reads(256) | problems(128)], K = 384
    gemm_hmma<<<gg, 256, 2 * BUFB>>>(rhi, rlo, DV, DV, pbhi, pblo, DK,
                                     wohi, wolo, DV + DK, w_out_b, out, /*tanh*/1);
}